// round 5
// baseline (speedup 1.0000x reference)
#include <cuda_runtime.h>

#define CC   10
#define HH   30
#define WW   30
#define DD   11
#define FULL 0xFFFFFFFFu

__device__ __forceinline__ float rsum16(float v) {
    #pragma unroll
    for (int o = 1; o < 16; o <<= 1) v += __shfl_xor_sync(FULL, v, o);
    return v;
}

__global__ __launch_bounds__(256) void pve_fused(
    const float* __restrict__ x,      // [2,10,30,30] one-hot
    const float* __restrict__ w_in,   // [33,11]
    const float* __restrict__ w_out,  // [11,11]
    const float* __restrict__ w_ff1,  // [1,11]
    const float* __restrict__ w_ff2,  // [11,1]
    const float* __restrict__ ln1_g,  // [11]
    const float* __restrict__ ln2_g,  // [11]
    float* __restrict__ out)          // [1800,10,100]
{
    __shared__ unsigned char ctile[10][10]; // classes for shared 10x10 region
    __shared__ unsigned int  wtab[4][25];   // packed slot classes, per pixel
    __shared__ float         pvs[4][10];    // padding softmax vec, per pixel

    const int tid  = threadIdx.x;
    const int lane = tid & 31;
    const int w    = tid >> 5;              // warp 0..7

    const int blk = blockIdx.x;             // 450 = 2 imgs x 15 x 15 tiles
    const int n   = blk / 225;
    const int t   = blk % 225;
    const int pi0 = (t / 15) * 2;
    const int pj0 = (t % 15) * 2;

    // ── decode the shared 10x10 class region (one-hot -> class via dot) ──
    if (tid < 100) {
        int rr = tid / 10, cc2 = tid % 10;
        int si = pi0 - 4 + rr, sj = pj0 - 4 + cc2;
        int cls = 10;
        if (si >= 0 && si < HH && sj >= 0 && sj < WW) {
            const float* px = x + ((long)n * CC * HH + si) * WW + sj;
            float acc = 0.f;
            #pragma unroll
            for (int c = 1; c < CC; c++) acc += (float)c * px[c * HH * WW];
            cls = __float2int_rn(acc);
        }
        ctile[rr][cc2] = (unsigned char)cls;
    }
    __syncthreads();

    // ── build word table: thread (p,j) packs slots l=4j..4j+3 of pixel p ──
    if (tid < 100) {
        int p = tid / 25, j = tid % 25;
        int dpi = p >> 1, dpj = p & 1;
        unsigned int wordv = 0;
        #pragma unroll
        for (int e = 0; e < 4; e++) {
            int l  = 4 * j + e;
            int mh = l / 10, mw = l % 10;
            unsigned int cls = 255;
            if (mh < 9 && mw < 9) cls = ctile[dpi + mh][dpj + mw];
            wordv |= cls << (8 * e);
        }
        wtab[p][j] = wordv;
    }
    __syncthreads();

    // ── border pipeline: warp w (<4) handles pixel w ──
    if (w < 4) {
        const int dpi = w >> 1, dpj = w & 1;
        const int pi = pi0 + dpi, pj = pj0 + dpj;
        const bool haspad = (pi < 4) | (pi > HH - 5) | (pj < 4) | (pj > WW - 5);
        if (haspad) {
            unsigned int word = (lane < 25) ? wtab[w][lane] : 0xFFFFFFFFu;
            const int d = lane;
            float kk[DD], vv[DD], q10 = 0.f;
            if (d < DD) {
                q10 = w_in[d * DD + 10];
                #pragma unroll
                for (int c = 0; c < DD; c++) {
                    kk[c] = w_in[(DD + d) * DD + c];
                    vv[c] = w_in[(2 * DD + d) * DD + c];
                }
            }
            // fused histogram (vcmp+popc+redux) + attention
            float num = 0.f, den = 0.f;
            #pragma unroll
            for (int c = 0; c < DD; c++) {
                unsigned int eq  = __vcmpeq4(word, c * 0x01010101u);
                int          cnt = __popc(eq) >> 3;
                int          hc  = __reduce_add_sync(FULL, cnt);
                if (d < DD) {
                    float e = __expf(q10 * kk[c]) * (float)hc;
                    den += e;
                    num += e * vv[c];
                }
            }
            float ao = (d < DD) ? num / den : 0.f;

            // svec = e_10 + ao @ w_out^T
            float acc = (d == 10) ? 1.f : 0.f;
            #pragma unroll
            for (int c = 0; c < DD; c++) {
                float a = __shfl_sync(FULL, ao, c);
                if (d < DD) acc += a * w_out[d * DD + c];
            }
            float sv = (d < DD) ? acc : 0.f;

            // LN1 (mean + E[x^2], independent chains)
            float s1 = rsum16(sv);
            float s2 = rsum16(sv * sv);
            float m   = s1 * (1.f / 11.f);
            float var = fmaxf(s2 * (1.f / 11.f) - m * m, 0.f);
            float inv = rsqrtf(var + 1e-5f);
            float h1  = (d < DD) ? (sv - m) * inv * ln1_g[d] : 0.f;

            // FF
            float tt = rsum16((d < DD) ? h1 * w_ff1[d] : 0.f);
            tt = fmaxf(tt, 0.f);
            float h2 = (d < DD) ? h1 + tt * w_ff2[d] : 0.f;

            // LN2
            float t1 = rsum16(h2);
            float t2 = rsum16(h2 * h2);
            float m2   = t1 * (1.f / 11.f);
            float var2 = fmaxf(t2 * (1.f / 11.f) - m2 * m2, 0.f);
            float inv2 = rsqrtf(var2 + 1e-5f);
            float hhv  = (d < DD) ? (h2 - m2) * inv2 * ln2_g[d] : 0.f;

            // softmax over classes 0..9 (values bounded post-LN: no max-sub)
            float ex = (d < CC) ? __expf(hhv) : 0.f;
            float se = rsum16(ex);
            if (d < CC) pvs[w][d] = ex / se;
        }
    }
    __syncthreads();

    // ── scatter: 4 pixels x 250 float4, shared by all 256 threads ──
    #pragma unroll
    for (int it = 0; it < 4; it++) {
        int g = tid + it * 256;
        if (g < 1000) {
            int p = g / 250;
            int q = g - p * 250;
            int c = q / 25;
            int j = q - c * 25;
            int pi = pi0 + (p >> 1), pj = pj0 + (p & 1);
            long b = (long)((n * HH + pi) * WW + pj);
            unsigned int wd = wtab[p][j];
            float        pc = pvs[p][c];   // only consumed when a slot==10
            float4 r;
            float* rp = &r.x;
            #pragma unroll
            for (int e = 0; e < 4; e++) {
                unsigned int cls = (wd >> (8 * e)) & 0xFF;
                // cls==255 (masked) fails both compares -> 0
                rp[e] = (cls == 10u) ? pc : ((cls == (unsigned)c) ? 1.0f : 0.0f);
            }
            reinterpret_cast<float4*>(out + b * 1000)[q] = r;
        }
    }
}

extern "C" void kernel_launch(void* const* d_in, const int* in_sizes, int n_in,
                              void* d_out, int out_size) {
    const float* x     = (const float*)d_in[0];
    const float* w_in  = (const float*)d_in[1];
    const float* w_out = (const float*)d_in[2];
    const float* w_ff1 = (const float*)d_in[3];
    const float* w_ff2 = (const float*)d_in[4];
    const float* ln1_g = (const float*)d_in[5];
    const float* ln2_g = (const float*)d_in[6];

    pve_fused<<<450, 256>>>(x, w_in, w_out, w_ff1, w_ff2, ln1_g, ln2_g,
                            (float*)d_out);
}

// round 6
// speedup vs baseline: 1.1895x; 1.1895x over previous
#include <cuda_runtime.h>

#define CC   10
#define HH   30
#define WW   30
#define DD   11
#define PMH  38          // padded map height  (30 + 2*4)
#define PMW  40          // padded map row stride (38 cols + 2 pad)
#define FULL 0xFFFFFFFFu

// Padded per-pixel class map: value 10 outside the image (= padding token).
__device__ unsigned char g_map[2 * PMH * PMW];

__global__ __launch_bounds__(128) void decode_kernel(const float* __restrict__ x) {
    int t = blockIdx.x * 128 + threadIdx.x;
    if (t >= 2 * PMH * PMW) return;
    int n  = t / (PMH * PMW);
    int rc = t % (PMH * PMW);
    int r  = rc / PMW, c = rc % PMW;
    int si = r - 4, sj = c - 4;
    int cls = 10;
    if (si >= 0 && si < HH && sj >= 0 && sj < WW) {
        const float* px = x + ((long)n * CC * HH + si) * WW + sj;
        float acc = 0.f;
        #pragma unroll
        for (int cc2 = 1; cc2 < CC; cc2++) acc += (float)cc2 * px[cc2 * HH * WW];
        cls = __float2int_rn(acc);
    }
    g_map[t] = (unsigned char)cls;
}

__device__ __forceinline__ float rsum16(float v) {
    #pragma unroll
    for (int o = 1; o < 16; o <<= 1) v += __shfl_xor_sync(FULL, v, o);
    return v;
}

__global__ __launch_bounds__(128) void pve_kernel(
    const float* __restrict__ w_in,   // [33,11]
    const float* __restrict__ w_out,  // [11,11]
    const float* __restrict__ w_ff1,  // [1,11]
    const float* __restrict__ w_ff2,  // [11,1]
    const float* __restrict__ ln1_g,  // [11]
    const float* __restrict__ ln2_g,  // [11]
    float* __restrict__ out)          // [1800,10,100]
{
    __shared__ unsigned char ctile[10][10];  // classes for shared 10x10 region
    __shared__ unsigned int  wtab[4][25];    // packed slot classes, per pixel
    __shared__ float         pvs[4][10];     // padding softmax vec, per pixel

    const int tid  = threadIdx.x;
    const int lane = tid & 31;
    const int w    = tid >> 5;               // warp 0..3, one pixel each

    const int blk = blockIdx.x;              // 450 = 2 imgs x 15 x 15 tiles
    const int n   = blk / 225;
    const int t   = blk % 225;
    const int pi0 = (t / 15) * 2;
    const int pj0 = (t % 15) * 2;

    // ── phase 1: pull the 10x10 class region from the padded map ──
    if (tid < 100) {
        int rr = tid / 10, cc2 = tid % 10;
        ctile[rr][cc2] = g_map[(n * PMH + pi0 + rr) * PMW + pj0 + cc2];
    }
    __syncthreads();   // the ONLY block barrier

    // ── phase 2 (warp-local): word build + optional border pipeline ──
    const int dpi = w >> 1, dpj = w & 1;
    const int pi = pi0 + dpi, pj = pj0 + dpj;
    const bool haspad = (pi < 4) | (pi > HH - 5) | (pj < 4) | (pj > WW - 5);

    unsigned int word = 0xFFFFFFFFu;
    if (lane < 25) {
        word = 0;
        #pragma unroll
        for (int e = 0; e < 4; e++) {
            int l  = 4 * lane + e;
            int mh = l / 10, mw = l % 10;
            unsigned int cls = 255;
            if (mh < 9 && mw < 9) cls = ctile[dpi + mh][dpj + mw];
            word |= cls << (8 * e);
        }
        wtab[w][lane] = word;
    }

    if (haspad) {
        const int d = lane;
        float kk[DD], vv[DD], q10 = 0.f;
        if (d < DD) {
            q10 = w_in[d * DD + 10];
            #pragma unroll
            for (int c = 0; c < DD; c++) {
                kk[c] = w_in[(DD + d) * DD + c];
                vv[c] = w_in[(2 * DD + d) * DD + c];
            }
        }
        // fused histogram (vcmp+popc+redux) + attention for query class 10
        float num = 0.f, den = 0.f;
        #pragma unroll
        for (int c = 0; c < DD; c++) {
            unsigned int eq  = __vcmpeq4(word, c * 0x01010101u);
            int          cnt = __popc(eq) >> 3;
            int          hc  = __reduce_add_sync(FULL, cnt);
            if (d < DD) {
                float e = __expf(q10 * kk[c]) * (float)hc;
                den += e;
                num += e * vv[c];
            }
        }
        float ao = (d < DD) ? num / den : 0.f;

        // svec = e_10 + ao @ w_out^T
        float acc = (d == 10) ? 1.f : 0.f;
        #pragma unroll
        for (int c = 0; c < DD; c++) {
            float a = __shfl_sync(FULL, ao, c);
            if (d < DD) acc += a * w_out[d * DD + c];
        }
        float sv = (d < DD) ? acc : 0.f;

        // LN1 (mean & E[x^2] as independent reduction chains)
        float s1 = rsum16(sv);
        float s2 = rsum16(sv * sv);
        float m   = s1 * (1.f / 11.f);
        float var = fmaxf(s2 * (1.f / 11.f) - m * m, 0.f);
        float inv = rsqrtf(var + 1e-5f);
        float h1  = (d < DD) ? (sv - m) * inv * ln1_g[d] : 0.f;

        // FF
        float tt = rsum16((d < DD) ? h1 * w_ff1[d] : 0.f);
        tt = fmaxf(tt, 0.f);
        float h2 = (d < DD) ? h1 + tt * w_ff2[d] : 0.f;

        // LN2
        float t1 = rsum16(h2);
        float t2 = rsum16(h2 * h2);
        float m2   = t1 * (1.f / 11.f);
        float var2 = fmaxf(t2 * (1.f / 11.f) - m2 * m2, 0.f);
        float inv2 = rsqrtf(var2 + 1e-5f);
        float hhv  = (d < DD) ? (h2 - m2) * inv2 * ln2_g[d] : 0.f;

        // softmax over classes 0..9 (post-LN values bounded: no max-sub)
        float ex = (d < CC) ? __expf(hhv) : 0.f;
        float se = rsum16(ex);
        if (d < CC) pvs[w][d] = ex / se;
    }
    __syncwarp();

    // ── phase 3 (warp-local): scatter 250 float4, coalesced (q = c*25+j) ──
    float4* o4 = reinterpret_cast<float4*>(out + (long)((n * HH + pi) * WW + pj) * 1000);
    #pragma unroll
    for (int it = 0; it < 8; it++) {
        int q = lane + it * 32;
        if (q < 250) {
            int c = q / 25;
            int j = q - c * 25;
            unsigned int wd = wtab[w][j];
            float        pc = pvs[w][c];   // consumed only when a slot==10
            float4 r;
            float* rp = &r.x;
            #pragma unroll
            for (int e = 0; e < 4; e++) {
                unsigned int cls = (wd >> (8 * e)) & 0xFF;
                rp[e] = (cls == 10u) ? pc : ((cls == (unsigned)c) ? 1.0f : 0.0f);
            }
            o4[q] = r;
        }
    }
}

extern "C" void kernel_launch(void* const* d_in, const int* in_sizes, int n_in,
                              void* d_out, int out_size) {
    const float* x     = (const float*)d_in[0];
    const float* w_in  = (const float*)d_in[1];
    const float* w_out = (const float*)d_in[2];
    const float* w_ff1 = (const float*)d_in[3];
    const float* w_ff2 = (const float*)d_in[4];
    const float* ln1_g = (const float*)d_in[5];
    const float* ln2_g = (const float*)d_in[6];

    decode_kernel<<<(2 * PMH * PMW + 127) / 128, 128>>>(x);
    pve_kernel<<<450, 128>>>(w_in, w_out, w_ff1, w_ff2, ln1_g, ln2_g,
                             (float*)d_out);
}

// round 7
// speedup vs baseline: 1.2710x; 1.0685x over previous
#include <cuda_runtime.h>

#define CC   10
#define HH   30
#define WW   30
#define DD   11
#define PMH  38          // padded map height  (30 + 2*4)
#define PMW  40          // padded map row stride
#define FULL 0xFFFFFFFFu

// Padded per-pixel class map: value 10 outside the image (= padding token).
__device__ unsigned char g_map[2 * PMH * PMW];

__global__ __launch_bounds__(128) void decode_kernel(const float* __restrict__ x) {
    int t = blockIdx.x * 128 + threadIdx.x;
    if (t >= 2 * PMH * PMW) return;
    int n  = t / (PMH * PMW);
    int rc = t % (PMH * PMW);
    int r  = rc / PMW, c = rc % PMW;
    int si = r - 4, sj = c - 4;
    int cls = 10;
    if (si >= 0 && si < HH && sj >= 0 && sj < WW) {
        const float* px = x + ((long)n * CC * HH + si) * WW + sj;
        float acc = 0.f;
        #pragma unroll
        for (int cc2 = 1; cc2 < CC; cc2++) acc += (float)cc2 * px[cc2 * HH * WW];
        cls = __float2int_rn(acc);
    }
    g_map[t] = (unsigned char)cls;
}

__device__ __forceinline__ float rsum16(float v) {
    #pragma unroll
    for (int o = 1; o < 16; o <<= 1) v += __shfl_xor_sync(FULL, v, o);
    return v;
}

__global__ __launch_bounds__(32) void pve_kernel(
    const float* __restrict__ w_in,   // [33,11]
    const float* __restrict__ w_out,  // [11,11]
    const float* __restrict__ w_ff1,  // [1,11]
    const float* __restrict__ w_ff2,  // [11,1]
    const float* __restrict__ ln1_g,  // [11]
    const float* __restrict__ ln2_g,  // [11]
    float* __restrict__ out)          // [1800,10,100]
{
    __shared__ unsigned int wtab[25];
    __shared__ float        pvs[10];

    const int lane = threadIdx.x;
    const int b    = blockIdx.x;            // pixel id 0..1799
    const int n    = b / 900;
    const int rem  = b % 900;
    const int pi   = rem / 30, pj = rem % 30;

    const bool haspad = (pi < 4) | (pi > HH - 5) | (pj < 4) | (pj > WW - 5);

    // ── hoist weight loads so they overlap the map loads (border only) ──
    const int d = lane;
    float kk[DD], vv[DD], wo[DD];
    float q10 = 0.f, g1 = 0.f, g2 = 0.f, f1 = 0.f, f2 = 0.f;
    if (haspad && d < DD) {
        q10 = w_in[d * DD + 10];
        g1  = ln1_g[d];
        g2  = ln2_g[d];
        f1  = w_ff1[d];
        f2  = w_ff2[d];
        #pragma unroll
        for (int c = 0; c < DD; c++) {
            kk[c] = w_in[(DD + d) * DD + c];
            vv[c] = w_in[(2 * DD + d) * DD + c];
            wo[c] = w_out[d * DD + c];
        }
    }

    // ── word build: lane j (<25) packs slots l = 4j..4j+3 ──
    unsigned int word = 0xFFFFFFFFu;
    if (lane < 25) {
        const unsigned char* mp = g_map + (n * PMH + pi) * PMW + pj;
        word = 0;
        #pragma unroll
        for (int e = 0; e < 4; e++) {
            int l  = 4 * lane + e;
            int mh = l / 10, mw = l % 10;
            unsigned int cls = 255;
            if (mh < 9 && mw < 9) cls = mp[mh * PMW + mw];
            word |= cls << (8 * e);
        }
        wtab[lane] = word;
    }

    if (haspad) {
        // fused histogram (vcmp+popc+redux) + attention for query class 10
        float num = 0.f, den = 0.f;
        #pragma unroll
        for (int c = 0; c < DD; c++) {
            unsigned int eq  = __vcmpeq4(word, c * 0x01010101u);
            int          cnt = __popc(eq) >> 3;
            int          hc  = __reduce_add_sync(FULL, cnt);
            if (d < DD) {
                float e = __expf(q10 * kk[c]) * (float)hc;
                den += e;
                num += e * vv[c];
            }
        }
        float ao = (d < DD) ? num / den : 0.f;

        // svec = e_10 + ao @ w_out^T
        float acc = (d == 10) ? 1.f : 0.f;
        #pragma unroll
        for (int c = 0; c < DD; c++) {
            float a = __shfl_sync(FULL, ao, c);
            if (d < DD) acc += a * wo[c];
        }
        float sv = (d < DD) ? acc : 0.f;

        // LN1 (mean & E[x^2], independent chains)
        float s1 = rsum16(sv);
        float s2 = rsum16(sv * sv);
        float m   = s1 * (1.f / 11.f);
        float var = fmaxf(s2 * (1.f / 11.f) - m * m, 0.f);
        float inv = rsqrtf(var + 1e-5f);
        float h1  = (d < DD) ? (sv - m) * inv * g1 : 0.f;

        // FF
        float tt = rsum16(h1 * f1);
        tt = fmaxf(tt, 0.f);
        float h2 = (d < DD) ? h1 + tt * f2 : 0.f;

        // LN2
        float t1 = rsum16(h2);
        float t2 = rsum16(h2 * h2);
        float m2   = t1 * (1.f / 11.f);
        float var2 = fmaxf(t2 * (1.f / 11.f) - m2 * m2, 0.f);
        float inv2 = rsqrtf(var2 + 1e-5f);
        float hhv  = (d < DD) ? (h2 - m2) * inv2 * g2 : 0.f;

        // softmax over classes 0..9 (post-LN values bounded: no max-sub)
        float ex = (d < CC) ? __expf(hhv) : 0.f;
        float se = rsum16(ex);
        if (d < CC) pvs[d] = ex / se;
    }
    __syncwarp();

    // ── scatter 250 float4, coalesced (q = c*25 + j) ──
    float4* o4 = reinterpret_cast<float4*>(out + (long)b * 1000);
    #pragma unroll
    for (int it = 0; it < 8; it++) {
        int q = lane + it * 32;
        if (q < 250) {
            int c = q / 25;
            int j = q - c * 25;
            unsigned int wd = wtab[j];
            float        pc = haspad ? pvs[c] : 0.f;
            float4 r;
            float* rp = &r.x;
            #pragma unroll
            for (int e = 0; e < 4; e++) {
                unsigned int cls = (wd >> (8 * e)) & 0xFF;
                rp[e] = (cls == 10u) ? pc : ((cls == (unsigned)c) ? 1.0f : 0.0f);
            }
            o4[q] = r;
        }
    }
}

extern "C" void kernel_launch(void* const* d_in, const int* in_sizes, int n_in,
                              void* d_out, int out_size) {
    const float* x     = (const float*)d_in[0];
    const float* w_in  = (const float*)d_in[1];
    const float* w_out = (const float*)d_in[2];
    const float* w_ff1 = (const float*)d_in[3];
    const float* w_ff2 = (const float*)d_in[4];
    const float* ln1_g = (const float*)d_in[5];
    const float* ln2_g = (const float*)d_in[6];

    decode_kernel<<<(2 * PMH * PMW + 127) / 128, 128>>>(x);
    pve_kernel<<<1800, 32>>>(w_in, w_out, w_ff1, w_ff2, ln1_g, ln2_g,
                             (float*)d_out);
}

// round 8
// speedup vs baseline: 1.4676x; 1.1547x over previous
#include <cuda_runtime.h>

#define CC   10
#define HH   30
#define WW   30
#define DD   11
#define FULL 0xFFFFFFFFu

__device__ __forceinline__ float rsum16(float v) {
    #pragma unroll
    for (int o = 1; o < 16; o <<= 1) v += __shfl_xor_sync(FULL, v, o);
    return v;
}

__global__ __launch_bounds__(32) void pve_kernel(
    const float* __restrict__ x,      // [2,10,30,30] one-hot
    const float* __restrict__ w_in,   // [33,11]
    const float* __restrict__ w_out,  // [11,11]
    const float* __restrict__ w_ff1,  // [1,11]
    const float* __restrict__ w_ff2,  // [11,1]
    const float* __restrict__ ln1_g,  // [11]
    const float* __restrict__ ln2_g,  // [11]
    float* __restrict__ out)          // [1800,10,100]
{
    __shared__ unsigned int wtab[25];
    __shared__ float        pvs[10];

    const int lane = threadIdx.x;
    const int b    = blockIdx.x;            // pixel id 0..1799
    const int n    = b / 900;
    const int rem  = b % 900;
    const int pi   = rem / 30, pj = rem % 30;

    const bool haspad = (pi < 4) | (pi > HH - 5) | (pj < 4) | (pj > WW - 5);

    // ── hoist weight loads to overlap the decode loads (border warps) ──
    const int d = lane;
    float kk[DD], vv[DD], wo[DD];
    float q10 = 0.f, g1 = 0.f, g2 = 0.f, f1 = 0.f, f2 = 0.f;
    if (haspad && d < DD) {
        q10 = w_in[d * DD + 10];
        g1  = ln1_g[d];
        g2  = ln2_g[d];
        f1  = w_ff1[d];
        f2  = w_ff2[d];
        #pragma unroll
        for (int c = 0; c < DD; c++) {
            kk[c] = w_in[(DD + d) * DD + c];
            vv[c] = w_in[(2 * DD + d) * DD + c];
            wo[c] = w_out[d * DD + c];
        }
    }

    // ── decode + pack: lane j (<25) owns slots l = 4j..4j+3 ──
    // class = round(sum_{c>=1} c * x[c]) (x one-hot); OOB image -> 10.
    unsigned int word = 0xFFFFFFFFu;
    if (lane < 25) {
        const float* xn = x + (long)n * (CC * HH * WW);
        word = 0;
        #pragma unroll
        for (int e = 0; e < 4; e++) {
            int l  = 4 * lane + e;
            int mh = l / 10, mw = l % 10;
            unsigned int cls = 255;
            if (mh < 9 && mw < 9) {
                int si = pi + mh - 4, sj = pj + mw - 4;
                cls = 10;
                if (si >= 0 && si < HH && sj >= 0 && sj < WW) {
                    const float* px = xn + si * WW + sj;
                    float acc = 0.f;
                    #pragma unroll
                    for (int c = 1; c < CC; c++) acc += (float)c * px[c * HH * WW];
                    cls = __float2int_rn(acc);
                }
            }
            word |= cls << (8 * e);
        }
        wtab[lane] = word;
    }

    if (haspad) {
        // fused histogram (vcmp+popc+redux) + attention for query class 10
        float num = 0.f, den = 0.f;
        #pragma unroll
        for (int c = 0; c < DD; c++) {
            unsigned int eq  = __vcmpeq4(word, c * 0x01010101u);
            int          cnt = __popc(eq) >> 3;
            int          hc  = __reduce_add_sync(FULL, cnt);
            if (d < DD) {
                float e = __expf(q10 * kk[c]) * (float)hc;
                den += e;
                num += e * vv[c];
            }
        }
        float ao = (d < DD) ? num / den : 0.f;

        // svec = e_10 + ao @ w_out^T
        float acc = (d == 10) ? 1.f : 0.f;
        #pragma unroll
        for (int c = 0; c < DD; c++) {
            float a = __shfl_sync(FULL, ao, c);
            if (d < DD) acc += a * wo[c];
        }
        float sv = (d < DD) ? acc : 0.f;

        // LN1 (mean & E[x^2], independent reduction chains)
        float s1 = rsum16(sv);
        float s2 = rsum16(sv * sv);
        float m   = s1 * (1.f / 11.f);
        float var = fmaxf(s2 * (1.f / 11.f) - m * m, 0.f);
        float inv = rsqrtf(var + 1e-5f);
        float h1  = (d < DD) ? (sv - m) * inv * g1 : 0.f;

        // FF
        float tt = rsum16(h1 * f1);
        tt = fmaxf(tt, 0.f);
        float h2 = (d < DD) ? h1 + tt * f2 : 0.f;

        // LN2
        float t1 = rsum16(h2);
        float t2 = rsum16(h2 * h2);
        float m2   = t1 * (1.f / 11.f);
        float var2 = fmaxf(t2 * (1.f / 11.f) - m2 * m2, 0.f);
        float inv2 = rsqrtf(var2 + 1e-5f);
        float hhv  = (d < DD) ? (h2 - m2) * inv2 * g2 : 0.f;

        // softmax over classes 0..9 (post-LN values bounded: no max-sub)
        float ex = (d < CC) ? __expf(hhv) : 0.f;
        float se = rsum16(ex);
        if (d < CC) pvs[d] = ex / se;
    }
    __syncwarp();

    // ── scatter 250 float4, coalesced (q = c*25 + j) ──
    float4* o4 = reinterpret_cast<float4*>(out + (long)b * 1000);
    #pragma unroll
    for (int it = 0; it < 8; it++) {
        int q = lane + it * 32;
        if (q < 250) {
            int c = q / 25;
            int j = q - c * 25;
            unsigned int wd = wtab[j];
            float        pc = haspad ? pvs[c] : 0.f;
            float4 r;
            float* rp = &r.x;
            #pragma unroll
            for (int e = 0; e < 4; e++) {
                unsigned int cls = (wd >> (8 * e)) & 0xFF;
                rp[e] = (cls == 10u) ? pc : ((cls == (unsigned)c) ? 1.0f : 0.0f);
            }
            o4[q] = r;
        }
    }
}

extern "C" void kernel_launch(void* const* d_in, const int* in_sizes, int n_in,
                              void* d_out, int out_size) {
    const float* x     = (const float*)d_in[0];
    const float* w_in  = (const float*)d_in[1];
    const float* w_out = (const float*)d_in[2];
    const float* w_ff1 = (const float*)d_in[3];
    const float* w_ff2 = (const float*)d_in[4];
    const float* ln1_g = (const float*)d_in[5];
    const float* ln2_g = (const float*)d_in[6];

    pve_kernel<<<1800, 32>>>(x, w_in, w_out, w_ff1, w_ff2, ln1_g, ln2_g,
                             (float*)d_out);
}